// round 15
// baseline (speedup 1.0000x reference)
#include <cuda_runtime.h>
#include <cuda_fp16.h>
#include <math.h>
#include <stdint.h>

#define CIN   64
#define COUT  64
#define Hdim  96
#define Wdim  96
#define Bdim  8
#define HW    (Hdim*Wdim)     /* 9216  */
#define PTOT  (Bdim*HW)       /* 73728 */

// Scratch (no cudaMalloc allowed).
__device__ __half g_xt [PTOT*CIN + 128]; // NHWC x fp16: [(b*HW+h*96+w)*64 + c]
__device__ uint2  g_cfh[PTOT*9];         // packed half coefs {c00,c01},{c10,c11}
__device__ int2   g_bs [PTOT*9];         // clamped row bases (half-element offset)
__device__ uint4  g_wtmh[9*16*32];       // main weights fp16 fragment-major per tap
__device__ uint4  g_wo2h[9*4*2*32];      // offset weights fp16 fragment-major (2304)

// ---------------- helpers --------------------------------------------------
__device__ __forceinline__ void cp_async16(unsigned saddr, const void* g) {
    asm volatile("cp.async.cg.shared.global [%0], [%1], 16;" :: "r"(saddr), "l"(g));
}
__device__ __forceinline__ void cp_commit() { asm volatile("cp.async.commit_group;"); }
__device__ __forceinline__ void cp_wait0()  { asm volatile("cp.async.wait_group 0;"); }

// m16n8k16 fp16 MMA, fp32 accum
__device__ __forceinline__ void mma_f16(float4& d, uint32_t a0, uint32_t a1,
                                        uint32_t a2, uint32_t a3,
                                        uint32_t b0, uint32_t b1) {
    asm volatile("mma.sync.aligned.m16n8k16.row.col.f32.f16.f16.f32 "
        "{%0,%1,%2,%3}, {%4,%5,%6,%7}, {%8,%9}, {%0,%1,%2,%3};"
        : "+f"(d.x), "+f"(d.y), "+f"(d.z), "+f"(d.w)
        : "r"(a0), "r"(a1), "r"(a2), "r"(a3), "r"(b0), "r"(b1));
}

__device__ __forceinline__ void ldmA(uint32_t& a0, uint32_t& a1,
                                     uint32_t& a2, uint32_t& a3, unsigned addr) {
    asm volatile("ldmatrix.sync.aligned.m8n8.x4.shared.b16 {%0,%1,%2,%3}, [%4];"
        : "=r"(a0), "=r"(a1), "=r"(a2), "=r"(a3) : "r"(addr));
}

// meta math: (ys, xs, mask) -> coefs + clamped row bases (half-element units)
__device__ __forceinline__ void make_meta(float ys, float xs, float mk,
                                          float4& cf, int2& bs) {
    float y0f = floorf(ys), x0f = floorf(xs);
    float ty = ys - y0f, tx = xs - x0f;
    int iy0 = (int)y0f, ix0 = (int)x0f;
    float wy0 = (iy0 >= 0 && iy0 <= Hdim-1) ? (1.f - ty) : 0.f;
    float wy1 = (iy0+1 >= 0 && iy0+1 <= Hdim-1) ? ty : 0.f;
    float wx0 = (ix0 >= 0 && ix0 <= Wdim-1) ? (1.f - tx) : 0.f;
    float wx1 = (ix0+1 >= 0 && ix0+1 <= Wdim-1) ? tx : 0.f;
    int bx = min(max(ix0, 0), Wdim-1);
    float cx0 = (ix0 == bx) ? wx0 : ((ix0 + 1 == bx) ? wx1 : 0.f);
    float cx1 = (ix0 == bx) ? wx1 : 0.f;
    int cy0 = min(max(iy0,   0), Hdim-1);
    int cy1 = min(max(iy0+1, 0), Hdim-1);
    cf.x = wy0*cx0*mk;  cf.y = wy0*cx1*mk;
    cf.z = wy1*cx0*mk;  cf.w = wy1*cx1*mk;
    bs = make_int2((cy0*Wdim + bx)*64, (cy1*Wdim + bx)*64);
}

// ---------------------------------------------------------------------------
// Kernel A (fused prep): blocks 0..1151 transpose NCHW fp32 -> NHWC fp16
// (vectorized: float4 loads, packed half2 stores); blocks 1152..1169 pack
// both weight tensors into fp16 fragment layouts.
// ---------------------------------------------------------------------------
__global__ __launch_bounds__(256) void dc_prep(const float* __restrict__ x,
                                               const float* __restrict__ w,
                                               const float* __restrict__ wo)
{
    if (blockIdx.x < 1152) {
        __shared__ float tile[64*65];
        int b  = blockIdx.x / 144;
        int s0 = (blockIdx.x % 144) * 64;
        const float* xb = x + (size_t)b * CIN * HW + s0;
        // float4 loads: 64 c-rows x 16 float4
        for (int i = threadIdx.x; i < 64*16; i += 256) {
            int c = i >> 4, q = i & 15;
            float4 v = *(const float4*)(xb + (size_t)c*HW + q*4);
            tile[c*65 + q*4 + 0] = v.x;
            tile[c*65 + q*4 + 1] = v.y;
            tile[c*65 + q*4 + 2] = v.z;
            tile[c*65 + q*4 + 3] = v.w;
        }
        __syncthreads();
        // packed half2 stores: 64 s-rows x 32 half2 (128B per warp-row)
        __half* xtb = g_xt + ((size_t)b*HW + s0) * 64;
        for (int i = threadIdx.x; i < 64*32; i += 256) {
            int s = i >> 5, c2 = i & 31;
            __half2 h = __floats2half2_rn(tile[(2*c2)*65 + s],
                                          tile[(2*c2 + 1)*65 + s]);
            *(uint32_t*)(xtb + s*64 + 2*c2) = *(uint32_t*)&h;
        }
        if (blockIdx.x == 0 && threadIdx.x < 128)
            g_xt[(size_t)PTOT*CIN + threadIdx.x] = __float2half(0.f);
        return;
    }
    int i = (blockIdx.x - 1152) * 256 + threadIdx.x;
    if (i < 9*16*32) {       // main conv weights
        int k = i / 512, q = i % 512;
        int lane = q & 31, sp = q >> 5;
        int s = sp >> 2, ntp = sp & 3;
        unsigned short hs[8];
        #pragma unroll
        for (int j = 0; j < 8; j++) {
            int nt = 2*ntp + (j >> 2);
            int creg = (j >> 1) & 1;
            int c = s*16 + (lane & 3)*2 + (j & 1) + creg*8;
            int o = nt*8 + (lane >> 2);
            __half h = __float2half(w[(size_t)o*576 + c*9 + k]);
            hs[j] = *(unsigned short*)&h;
        }
        uint4 v;
        v.x = (uint32_t)hs[0] | ((uint32_t)hs[1] << 16);
        v.y = (uint32_t)hs[2] | ((uint32_t)hs[3] << 16);
        v.z = (uint32_t)hs[4] | ((uint32_t)hs[5] << 16);
        v.w = (uint32_t)hs[6] | ((uint32_t)hs[7] << 16);
        g_wtmh[i] = v;
    }
    if (i < 9*4*2*32) {      // offset conv weights (27 padded to 32 outputs)
        int kk = i / 256, q = i % 256;
        int lane = q & 31, sp = q >> 5;
        int s = sp >> 1, ntp = sp & 1;
        unsigned short hs[8];
        #pragma unroll
        for (int j = 0; j < 8; j++) {
            int nt = 2*ntp + (j >> 2);
            int creg = (j >> 1) & 1;
            int c = s*16 + (lane & 3)*2 + (j & 1) + creg*8;
            int m = nt*8 + (lane >> 2);
            float v = (m < 27) ? wo[(size_t)m*576 + c*9 + kk] : 0.f;
            __half h = __float2half(v);
            hs[j] = *(unsigned short*)&h;
        }
        uint4 v;
        v.x = (uint32_t)hs[0] | ((uint32_t)hs[1] << 16);
        v.y = (uint32_t)hs[2] | ((uint32_t)hs[3] << 16);
        v.z = (uint32_t)hs[4] | ((uint32_t)hs[5] << 16);
        v.w = (uint32_t)hs[6] | ((uint32_t)hs[7] << 16);
        g_wo2h[i] = v;
    }
}

// ---------------------------------------------------------------------------
// Kernel B: offset conv via mma.sync fp16 (m16n8k16) -> finished packed meta
// Block = TWO image rows (192 px), 384 threads = 12 warps.
// ---------------------------------------------------------------------------
#define BP_STR     104
#define B_SP_BYTES (4*98*BP_STR*2)           /* 81536 */
#define B_SB_OFF   B_SP_BYTES
#define B_SB_BYTES (9*4*2*32*16)             /* 36864 */
#define B_OM_OFF   (B_SB_OFF + B_SB_BYTES)   /* 118400 */
#define B_OM_BYTES (192*28*4)                /* 21504 */
#define B_SMEM_BYTES (B_OM_OFF + B_OM_BYTES) /* 139904 */

__global__ __launch_bounds__(384, 1) void dc_offsets(const float* __restrict__ b_off)
{
    extern __shared__ char smb[];
    __half* sPh = (__half*)smb;
    uint4*  sB4 = (uint4*)(smb + B_SB_OFF);
    float*  sOm = (float*)(smb + B_OM_OFF);
    unsigned sbBase = (unsigned)__cvta_generic_to_shared(sB4);

    int tid = threadIdx.x;
    int b   = blockIdx.x / (Hdim/2);
    int h0  = (blockIdx.x % (Hdim/2)) * 2;

    for (int i = tid; i < 2304; i += 384)
        cp_async16(sbBase + (unsigned)i*16u, g_wo2h + i);
    cp_commit();

    const __half* xtb = g_xt + (size_t)b * HW * 64;
    for (int r = 0; r < 4; r++) {
        int hh = h0 - 1 + r;
        bool rv = (hh >= 0) & (hh < Hdim);
        for (int i = tid; i < 98*32; i += 384) {
            int col = i >> 5, c2 = i & 31;
            int ww = col - 1;
            uint32_t v = 0;
            if (rv && ww >= 0 && ww < Wdim)
                v = *(const uint32_t*)(xtb + ((size_t)hh*Wdim + ww)*64 + c2*2);
            *(uint32_t*)(sPh + (r*98 + col)*BP_STR + c2*2) = v;
        }
    }
    cp_wait0();
    __syncthreads();

    int wid  = tid >> 5, lane = tid & 31;
    int g = lane >> 2, t = lane & 3;
    int rp  = wid >> 1;
    int ntp = wid & 1;
    int rowsel = rp / 3;
    int col0   = (rp % 3) * 32;

    float4 d00 = make_float4(0.f,0.f,0.f,0.f);
    float4 d01 = make_float4(0.f,0.f,0.f,0.f);
    float4 d10 = make_float4(0.f,0.f,0.f,0.f);
    float4 d11 = make_float4(0.f,0.f,0.f,0.f);

    #pragma unroll
    for (int kk = 0; kk < 9; kk++) {
        int ky = kk / 3, kx = kk % 3;
        const __half* ar0 = sPh + ((ky + rowsel)*98 + col0 + g + kx)*BP_STR;
        const __half* ar1 = ar0 + 16*BP_STR;
        #pragma unroll
        for (int s = 0; s < 4; s++) {
            int co = s*16 + t*2;
            uint32_t a00 = *(const uint32_t*)(ar0 + co);
            uint32_t a01 = *(const uint32_t*)(ar0 + 8*BP_STR + co);
            uint32_t a02 = *(const uint32_t*)(ar0 + co + 8);
            uint32_t a03 = *(const uint32_t*)(ar0 + 8*BP_STR + co + 8);
            uint32_t a10 = *(const uint32_t*)(ar1 + co);
            uint32_t a11 = *(const uint32_t*)(ar1 + 8*BP_STR + co);
            uint32_t a12 = *(const uint32_t*)(ar1 + co + 8);
            uint32_t a13 = *(const uint32_t*)(ar1 + 8*BP_STR + co + 8);
            uint4 bq = sB4[((kk*4 + s)*2 + ntp)*32 + lane];
            mma_f16(d00, a00,a01,a02,a03, bq.x, bq.y);
            mma_f16(d01, a00,a01,a02,a03, bq.z, bq.w);
            mma_f16(d10, a10,a11,a12,a13, bq.x, bq.y);
            mma_f16(d11, a10,a11,a12,a13, bq.z, bq.w);
        }
    }

    {
        int m0 = 16*ntp + 2*t;
        int m1 = 16*ntp + 8 + 2*t;
        int pxW = rowsel*96 + col0 + g;
        #pragma unroll
        for (int mt = 0; mt < 2; mt++) {
            float4 dv0 = mt ? d10 : d00;
            float4 dv1 = mt ? d11 : d01;
            int pA = pxW + mt*16, pB = pA + 8;
            sOm[pA*28 + m0] = dv0.x + __ldg(&b_off[m0]);
            sOm[pB*28 + m0] = dv0.z + __ldg(&b_off[m0]);
            if (m0 + 1 < 27) {
                sOm[pA*28 + m0+1] = dv0.y + __ldg(&b_off[m0+1]);
                sOm[pB*28 + m0+1] = dv0.w + __ldg(&b_off[m0+1]);
            }
            if (m1 < 27) {
                sOm[pA*28 + m1] = dv1.x + __ldg(&b_off[m1]);
                sOm[pB*28 + m1] = dv1.z + __ldg(&b_off[m1]);
            }
            if (m1 + 1 < 27) {
                sOm[pA*28 + m1+1] = dv1.y + __ldg(&b_off[m1+1]);
                sOm[pB*28 + m1+1] = dv1.w + __ldg(&b_off[m1+1]);
            }
        }
    }
    __syncthreads();

    for (int idx = tid; idx < 192*9; idx += 384) {
        int p2 = idx % 192, k = idx / 192;
        float dy = sOm[p2*28 + 2*k];
        float dx = sOm[p2*28 + 2*k + 1];
        float mv = sOm[p2*28 + 18 + k];
        float mask = 1.0f / (1.0f + __expf(-mv));
        int ky = k / 3, kx = k % 3;
        float ys = (float)(h0 + (p2/96) - 1 + ky) + dy;
        float xs = (float)((p2%96) - 1 + kx) + dx;
        float4 cf; int2 bs;
        make_meta(ys, xs, mask, cf, bs);
        int gi = (b*9 + k)*HW + h0*Wdim + p2;
        __half2 h01 = __floats2half2_rn(cf.x, cf.y);
        __half2 h23 = __floats2half2_rn(cf.z, cf.w);
        uint2 u;
        u.x = *(uint32_t*)&h01;
        u.y = *(uint32_t*)&h23;
        g_cfh[gi] = u;
        g_bs[gi]  = bs;
    }
}

// ---------------------------------------------------------------------------
// Kernel C: fused fp16 bilinear sample + mma.sync m16n8k16 GEMM. 3 blocks/SM.
// ---------------------------------------------------------------------------
#define C_SS0    0
#define C_SS1    18432
#define C_SB0    36864
#define C_SB1    45056
#define C_SMEM_BYTES 53248

__global__ __launch_bounds__(256, 3)
void dc_main(const float* __restrict__ bias, float* __restrict__ out)
{
    extern __shared__ char smc[];
    unsigned smem_base = (unsigned)__cvta_generic_to_shared(smc);

    int tid = threadIdx.x;
    int wid = tid >> 5, lane = tid & 31;
    int g = lane >> 2, t = lane & 3;
    int b      = blockIdx.x / 72;
    int pxBase = (blockIdx.x % 72) * 128;
    const __half* xh = g_xt + (size_t)b * HW * 64;
    int warpPx0 = wid * 16;
    int mq = wid & 3, oh = wid >> 2;
    int px0m = mq * 32;

    int gsel = lane >> 4;
    int gcol = (lane >> 3) & 1;
    int goct = lane & 7;

    int rowl = (lane & 7) + (((lane >> 3) & 1) << 3);
    unsigned aOff0 = (unsigned)((px0m + rowl) * 144 + ((lane >> 4) << 4));
    unsigned aOff1 = aOff0 + 16u*144u;

    float4 acc[8];
    #pragma unroll
    for (int a = 0; a < 8; a++) acc[a] = make_float4(0.f,0.f,0.f,0.f);

    const uint4* Bg = g_wtmh;

    auto gather_pair = [&](const int2* bsp, const uint2* cfp, int p0, unsigned dstOff) {
        int myPx = p0 + gsel;
        int2  bs = __ldg(&bsp[myPx]);
        uint2 cf = __ldg(&cfp[myPx]);
        const __half* r0 = xh + bs.x + gcol*64 + goct*8;
        const __half* r1 = xh + bs.y + gcol*64 + goct*8;
        uint4 qA = *(const uint4*)r0;
        uint4 qB = *(const uint4*)r1;
        __half2 cfx = *(__half2*)&cf.x;
        __half2 cfy = *(__half2*)&cf.y;
        __half2 cA = __half2half2(gcol ? __high2half(cfx) : __low2half(cfx));
        __half2 cB = __half2half2(gcol ? __high2half(cfy) : __low2half(cfy));
        __half2 v0 = __hfma2(*(__half2*)&qB.x, cB, __hmul2(*(__half2*)&qA.x, cA));
        __half2 v1 = __hfma2(*(__half2*)&qB.y, cB, __hmul2(*(__half2*)&qA.y, cA));
        __half2 v2 = __hfma2(*(__half2*)&qB.z, cB, __hmul2(*(__half2*)&qA.z, cA));
        __half2 v3 = __hfma2(*(__half2*)&qB.w, cB, __hmul2(*(__half2*)&qA.w, cA));
        uint32_t u0 = __shfl_xor_sync(0xffffffffu, *(uint32_t*)&v0, 8);
        uint32_t u1 = __shfl_xor_sync(0xffffffffu, *(uint32_t*)&v1, 8);
        uint32_t u2 = __shfl_xor_sync(0xffffffffu, *(uint32_t*)&v2, 8);
        uint32_t u3 = __shfl_xor_sync(0xffffffffu, *(uint32_t*)&v3, 8);
        __half2 w0 = __hadd2(v0, *(__half2*)&u0);
        __half2 w1 = __hadd2(v1, *(__half2*)&u1);
        __half2 w2 = __hadd2(v2, *(__half2*)&u2);
        __half2 w3 = __hadd2(v3, *(__half2*)&u3);
        if ((lane & 8) == 0) {
            unsigned addr = smem_base + dstOff + (unsigned)(myPx*144 + goct*16);
            asm volatile("st.shared.v4.b32 [%0], {%1, %2, %3, %4};"
                :: "r"(addr), "r"(*(uint32_t*)&w0), "r"(*(uint32_t*)&w1),
                   "r"(*(uint32_t*)&w2), "r"(*(uint32_t*)&w3));
        }
    };

    for (int i = tid; i < 512; i += 256)
        cp_async16(smem_base + C_SB0 + (unsigned)i*16u, Bg + i);
    cp_commit();
    {
        const int2*  bsp = g_bs  + (size_t)(b*9 + 0)*HW + pxBase;
        const uint2* cfp = g_cfh + (size_t)(b*9 + 0)*HW + pxBase;
        #pragma unroll
        for (int pq = 0; pq < 8; pq++)
            gather_pair(bsp, cfp, warpPx0 + pq*2, C_SS0);
    }
    cp_wait0();
    __syncthreads();

    for (int k = 0; k < 9; k++) {
        int cur = k & 1, nxt = cur ^ 1;
        if (k < 8) {
            unsigned dstB = smem_base + (nxt ? C_SB1 : C_SB0);
            const uint4* srcB = Bg + (size_t)(k+1)*512;
            for (int i = tid; i < 512; i += 256)
                cp_async16(dstB + (unsigned)i*16u, srcB + i);
            cp_commit();
        }
        unsigned ssAddr = smem_base + (cur ? C_SS1 : C_SS0);
        const uint4* sB4 = (const uint4*)(smc + (cur ? C_SB1 : C_SB0));
        unsigned gdst = (unsigned)(nxt ? C_SS1 : C_SS0);
        int kn = (k+1 < 9) ? k+1 : 0;
        const int2*  bsp = g_bs  + (size_t)(b*9 + kn)*HW + pxBase;
        const uint2* cfp = g_cfh + (size_t)(b*9 + kn)*HW + pxBase;

        #pragma unroll
        for (int ch = 0; ch < 4; ch++) {
            if (k < 8) {
                gather_pair(bsp, cfp, warpPx0 + ch*4,     gdst);
                gather_pair(bsp, cfp, warpPx0 + ch*4 + 2, gdst);
            }
            {
                uint32_t a00, a01, a02, a03, a10, a11, a12, a13;
                ldmA(a00, a01, a02, a03, ssAddr + aOff0 + (unsigned)ch*32u);
                ldmA(a10, a11, a12, a13, ssAddr + aOff1 + (unsigned)ch*32u);
                uint4 bq0 = sB4[(ch*4 + 2*oh    )*32 + lane];
                uint4 bq1 = sB4[(ch*4 + 2*oh + 1)*32 + lane];
                mma_f16(acc[0], a00,a01,a02,a03, bq0.x, bq0.y);
                mma_f16(acc[1], a00,a01,a02,a03, bq0.z, bq0.w);
                mma_f16(acc[2], a00,a01,a02,a03, bq1.x, bq1.y);
                mma_f16(acc[3], a00,a01,a02,a03, bq1.z, bq1.w);
                mma_f16(acc[4], a10,a11,a12,a13, bq0.x, bq0.y);
                mma_f16(acc[5], a10,a11,a12,a13, bq0.z, bq0.w);
                mma_f16(acc[6], a10,a11,a12,a13, bq1.x, bq1.y);
                mma_f16(acc[7], a10,a11,a12,a13, bq1.z, bq1.w);
            }
        }
        cp_wait0();
        __syncthreads();
    }

    float* sOut = (float*)smc;
    #pragma unroll
    for (int mt = 0; mt < 2; mt++)
        #pragma unroll
        for (int nt = 0; nt < 4; nt++) {
            float4 dv = acc[mt*4 + nt];
            int o = oh*32 + nt*8 + 2*t;
            int pA = px0m + mt*16 + g, pB = pA + 8;
            sOut[o*132 + pA]     = dv.x;
            sOut[(o+1)*132 + pA] = dv.y;
            sOut[o*132 + pB]     = dv.z;
            sOut[(o+1)*132 + pB] = dv.w;
        }
    __syncthreads();
    float* ob = out + (size_t)b * COUT * HW + pxBase;
    for (int i = tid; i < 64*128; i += 256) {
        int o = i >> 7, p = i & 127;
        ob[(size_t)o*HW + p] = sOut[o*132 + p] + __ldg(&bias[o]);
    }
}

// ---------------------------------------------------------------------------
extern "C" void kernel_launch(void* const* d_in, const int* in_sizes, int n_in,
                              void* d_out, int out_size)
{
    const float* x      = (const float*)d_in[0];
    const float* w_off  = (const float*)d_in[1];
    const float* b_off  = (const float*)d_in[2];
    const float* weight = (const float*)d_in[3];
    const float* bias   = (const float*)d_in[4];
    float* out = (float*)d_out;

    static bool attr_done = false;
    if (!attr_done) {
        cudaFuncSetAttribute(dc_offsets, cudaFuncAttributeMaxDynamicSharedMemorySize,
                             B_SMEM_BYTES);
        cudaFuncSetAttribute(dc_main, cudaFuncAttributeMaxDynamicSharedMemorySize,
                             C_SMEM_BYTES);
        attr_done = true;
    }

    dc_prep    <<<1152 + 18, 256>>>(x, weight, w_off);
    dc_offsets <<<Bdim * (Hdim/2), 384, B_SMEM_BYTES>>>(b_off);
    dc_main    <<<Bdim * 72, 256, C_SMEM_BYTES>>>(bias, out);
}

// round 16
// speedup vs baseline: 1.1042x; 1.1042x over previous
#include <cuda_runtime.h>
#include <cuda_fp16.h>
#include <math.h>
#include <stdint.h>

#define CIN   64
#define COUT  64
#define Hdim  96
#define Wdim  96
#define Bdim  8
#define HW    (Hdim*Wdim)     /* 9216  */
#define PTOT  (Bdim*HW)       /* 73728 */

// Scratch (no cudaMalloc allowed).
__device__ __half g_xt [PTOT*CIN + 128]; // NHWC x fp16: [(b*HW+h*96+w)*64 + c]
__device__ uint2  g_cfh[PTOT*9];         // packed half coefs {c00,c01},{c10,c11}
__device__ int2   g_bs [PTOT*9];         // clamped row bases (half-element offset)
__device__ uint4  g_wtmh[9*16*32];       // main weights fp16 fragment-major per tap
__device__ uint4  g_wo2h[9*4*2*32];      // offset weights fp16 fragment-major (2304)

// ---------------- helpers --------------------------------------------------
__device__ __forceinline__ void cp_async16(unsigned saddr, const void* g) {
    asm volatile("cp.async.cg.shared.global [%0], [%1], 16;" :: "r"(saddr), "l"(g));
}
__device__ __forceinline__ void cp_commit() { asm volatile("cp.async.commit_group;"); }
__device__ __forceinline__ void cp_wait0()  { asm volatile("cp.async.wait_group 0;"); }

// m16n8k16 fp16 MMA, fp32 accum
__device__ __forceinline__ void mma_f16(float4& d, uint32_t a0, uint32_t a1,
                                        uint32_t a2, uint32_t a3,
                                        uint32_t b0, uint32_t b1) {
    asm volatile("mma.sync.aligned.m16n8k16.row.col.f32.f16.f16.f32 "
        "{%0,%1,%2,%3}, {%4,%5,%6,%7}, {%8,%9}, {%0,%1,%2,%3};"
        : "+f"(d.x), "+f"(d.y), "+f"(d.z), "+f"(d.w)
        : "r"(a0), "r"(a1), "r"(a2), "r"(a3), "r"(b0), "r"(b1));
}

__device__ __forceinline__ void ldmA(uint32_t& a0, uint32_t& a1,
                                     uint32_t& a2, uint32_t& a3, unsigned addr) {
    asm volatile("ldmatrix.sync.aligned.m8n8.x4.shared.b16 {%0,%1,%2,%3}, [%4];"
        : "=r"(a0), "=r"(a1), "=r"(a2), "=r"(a3) : "r"(addr));
}

// meta math: (ys, xs, mask) -> coefs + clamped row bases (half-element units)
__device__ __forceinline__ void make_meta(float ys, float xs, float mk,
                                          float4& cf, int2& bs) {
    float y0f = floorf(ys), x0f = floorf(xs);
    float ty = ys - y0f, tx = xs - x0f;
    int iy0 = (int)y0f, ix0 = (int)x0f;
    float wy0 = (iy0 >= 0 && iy0 <= Hdim-1) ? (1.f - ty) : 0.f;
    float wy1 = (iy0+1 >= 0 && iy0+1 <= Hdim-1) ? ty : 0.f;
    float wx0 = (ix0 >= 0 && ix0 <= Wdim-1) ? (1.f - tx) : 0.f;
    float wx1 = (ix0+1 >= 0 && ix0+1 <= Wdim-1) ? tx : 0.f;
    int bx = min(max(ix0, 0), Wdim-1);
    float cx0 = (ix0 == bx) ? wx0 : ((ix0 + 1 == bx) ? wx1 : 0.f);
    float cx1 = (ix0 == bx) ? wx1 : 0.f;
    int cy0 = min(max(iy0,   0), Hdim-1);
    int cy1 = min(max(iy0+1, 0), Hdim-1);
    cf.x = wy0*cx0*mk;  cf.y = wy0*cx1*mk;
    cf.z = wy1*cx0*mk;  cf.w = wy1*cx1*mk;
    bs = make_int2((cy0*Wdim + bx)*64, (cy1*Wdim + bx)*64);
}

// ---------------------------------------------------------------------------
// Kernel A (fused prep): blocks 0..1151 transpose NCHW fp32 -> NHWC fp16
// (vectorized); blocks 1152..1169 pack weights into fp16 fragment layouts.
// ---------------------------------------------------------------------------
__global__ __launch_bounds__(256) void dc_prep(const float* __restrict__ x,
                                               const float* __restrict__ w,
                                               const float* __restrict__ wo)
{
    if (blockIdx.x < 1152) {
        __shared__ float tile[64*65];
        int b  = blockIdx.x / 144;
        int s0 = (blockIdx.x % 144) * 64;
        const float* xb = x + (size_t)b * CIN * HW + s0;
        for (int i = threadIdx.x; i < 64*16; i += 256) {
            int c = i >> 4, q = i & 15;
            float4 v = *(const float4*)(xb + (size_t)c*HW + q*4);
            tile[c*65 + q*4 + 0] = v.x;
            tile[c*65 + q*4 + 1] = v.y;
            tile[c*65 + q*4 + 2] = v.z;
            tile[c*65 + q*4 + 3] = v.w;
        }
        __syncthreads();
        __half* xtb = g_xt + ((size_t)b*HW + s0) * 64;
        for (int i = threadIdx.x; i < 64*32; i += 256) {
            int s = i >> 5, c2 = i & 31;
            __half2 h = __floats2half2_rn(tile[(2*c2)*65 + s],
                                          tile[(2*c2 + 1)*65 + s]);
            *(uint32_t*)(xtb + s*64 + 2*c2) = *(uint32_t*)&h;
        }
        if (blockIdx.x == 0 && threadIdx.x < 128)
            g_xt[(size_t)PTOT*CIN + threadIdx.x] = __float2half(0.f);
        return;
    }
    int i = (blockIdx.x - 1152) * 256 + threadIdx.x;
    if (i < 9*16*32) {       // main conv weights
        int k = i / 512, q = i % 512;
        int lane = q & 31, sp = q >> 5;
        int s = sp >> 2, ntp = sp & 3;
        unsigned short hs[8];
        #pragma unroll
        for (int j = 0; j < 8; j++) {
            int nt = 2*ntp + (j >> 2);
            int creg = (j >> 1) & 1;
            int c = s*16 + (lane & 3)*2 + (j & 1) + creg*8;
            int o = nt*8 + (lane >> 2);
            __half h = __float2half(w[(size_t)o*576 + c*9 + k]);
            hs[j] = *(unsigned short*)&h;
        }
        uint4 v;
        v.x = (uint32_t)hs[0] | ((uint32_t)hs[1] << 16);
        v.y = (uint32_t)hs[2] | ((uint32_t)hs[3] << 16);
        v.z = (uint32_t)hs[4] | ((uint32_t)hs[5] << 16);
        v.w = (uint32_t)hs[6] | ((uint32_t)hs[7] << 16);
        g_wtmh[i] = v;
    }
    if (i < 9*4*2*32) {      // offset conv weights (27 padded to 32 outputs)
        int kk = i / 256, q = i % 256;
        int lane = q & 31, sp = q >> 5;
        int s = sp >> 1, ntp = sp & 1;
        unsigned short hs[8];
        #pragma unroll
        for (int j = 0; j < 8; j++) {
            int nt = 2*ntp + (j >> 2);
            int creg = (j >> 1) & 1;
            int c = s*16 + (lane & 3)*2 + (j & 1) + creg*8;
            int m = nt*8 + (lane >> 2);
            float v = (m < 27) ? wo[(size_t)m*576 + c*9 + kk] : 0.f;
            __half h = __float2half(v);
            hs[j] = *(unsigned short*)&h;
        }
        uint4 v;
        v.x = (uint32_t)hs[0] | ((uint32_t)hs[1] << 16);
        v.y = (uint32_t)hs[2] | ((uint32_t)hs[3] << 16);
        v.z = (uint32_t)hs[4] | ((uint32_t)hs[5] << 16);
        v.w = (uint32_t)hs[6] | ((uint32_t)hs[7] << 16);
        g_wo2h[i] = v;
    }
}

// ---------------------------------------------------------------------------
// Kernel B: offset conv via mma.sync fp16 (m16n8k16) -> finished packed meta
// Block = TWO image rows (192 px), 384 threads = 12 warps.
// ---------------------------------------------------------------------------
#define BP_STR     104
#define B_SP_BYTES (4*98*BP_STR*2)           /* 81536 */
#define B_SB_OFF   B_SP_BYTES
#define B_SB_BYTES (9*4*2*32*16)             /* 36864 */
#define B_OM_OFF   (B_SB_OFF + B_SB_BYTES)   /* 118400 */
#define B_OM_BYTES (192*28*4)                /* 21504 */
#define B_SMEM_BYTES (B_OM_OFF + B_OM_BYTES) /* 139904 */

__global__ __launch_bounds__(384, 1) void dc_offsets(const float* __restrict__ b_off)
{
    extern __shared__ char smb[];
    __half* sPh = (__half*)smb;
    uint4*  sB4 = (uint4*)(smb + B_SB_OFF);
    float*  sOm = (float*)(smb + B_OM_OFF);
    unsigned sbBase = (unsigned)__cvta_generic_to_shared(sB4);

    int tid = threadIdx.x;
    int b   = blockIdx.x / (Hdim/2);
    int h0  = (blockIdx.x % (Hdim/2)) * 2;

    for (int i = tid; i < 2304; i += 384)
        cp_async16(sbBase + (unsigned)i*16u, g_wo2h + i);
    cp_commit();

    const __half* xtb = g_xt + (size_t)b * HW * 64;
    for (int r = 0; r < 4; r++) {
        int hh = h0 - 1 + r;
        bool rv = (hh >= 0) & (hh < Hdim);
        for (int i = tid; i < 98*32; i += 384) {
            int col = i >> 5, c2 = i & 31;
            int ww = col - 1;
            uint32_t v = 0;
            if (rv && ww >= 0 && ww < Wdim)
                v = *(const uint32_t*)(xtb + ((size_t)hh*Wdim + ww)*64 + c2*2);
            *(uint32_t*)(sPh + (r*98 + col)*BP_STR + c2*2) = v;
        }
    }
    cp_wait0();
    __syncthreads();

    int wid  = tid >> 5, lane = tid & 31;
    int g = lane >> 2, t = lane & 3;
    int rp  = wid >> 1;
    int ntp = wid & 1;
    int rowsel = rp / 3;
    int col0   = (rp % 3) * 32;

    float4 d00 = make_float4(0.f,0.f,0.f,0.f);
    float4 d01 = make_float4(0.f,0.f,0.f,0.f);
    float4 d10 = make_float4(0.f,0.f,0.f,0.f);
    float4 d11 = make_float4(0.f,0.f,0.f,0.f);

    #pragma unroll
    for (int kk = 0; kk < 9; kk++) {
        int ky = kk / 3, kx = kk % 3;
        const __half* ar0 = sPh + ((ky + rowsel)*98 + col0 + g + kx)*BP_STR;
        const __half* ar1 = ar0 + 16*BP_STR;
        #pragma unroll
        for (int s = 0; s < 4; s++) {
            int co = s*16 + t*2;
            uint32_t a00 = *(const uint32_t*)(ar0 + co);
            uint32_t a01 = *(const uint32_t*)(ar0 + 8*BP_STR + co);
            uint32_t a02 = *(const uint32_t*)(ar0 + co + 8);
            uint32_t a03 = *(const uint32_t*)(ar0 + 8*BP_STR + co + 8);
            uint32_t a10 = *(const uint32_t*)(ar1 + co);
            uint32_t a11 = *(const uint32_t*)(ar1 + 8*BP_STR + co);
            uint32_t a12 = *(const uint32_t*)(ar1 + co + 8);
            uint32_t a13 = *(const uint32_t*)(ar1 + 8*BP_STR + co + 8);
            uint4 bq = sB4[((kk*4 + s)*2 + ntp)*32 + lane];
            mma_f16(d00, a00,a01,a02,a03, bq.x, bq.y);
            mma_f16(d01, a00,a01,a02,a03, bq.z, bq.w);
            mma_f16(d10, a10,a11,a12,a13, bq.x, bq.y);
            mma_f16(d11, a10,a11,a12,a13, bq.z, bq.w);
        }
    }

    {
        int m0 = 16*ntp + 2*t;
        int m1 = 16*ntp + 8 + 2*t;
        int pxW = rowsel*96 + col0 + g;
        #pragma unroll
        for (int mt = 0; mt < 2; mt++) {
            float4 dv0 = mt ? d10 : d00;
            float4 dv1 = mt ? d11 : d01;
            int pA = pxW + mt*16, pB = pA + 8;
            sOm[pA*28 + m0] = dv0.x + __ldg(&b_off[m0]);
            sOm[pB*28 + m0] = dv0.z + __ldg(&b_off[m0]);
            if (m0 + 1 < 27) {
                sOm[pA*28 + m0+1] = dv0.y + __ldg(&b_off[m0+1]);
                sOm[pB*28 + m0+1] = dv0.w + __ldg(&b_off[m0+1]);
            }
            if (m1 < 27) {
                sOm[pA*28 + m1] = dv1.x + __ldg(&b_off[m1]);
                sOm[pB*28 + m1] = dv1.z + __ldg(&b_off[m1]);
            }
            if (m1 + 1 < 27) {
                sOm[pA*28 + m1+1] = dv1.y + __ldg(&b_off[m1+1]);
                sOm[pB*28 + m1+1] = dv1.w + __ldg(&b_off[m1+1]);
            }
        }
    }
    __syncthreads();

    for (int idx = tid; idx < 192*9; idx += 384) {
        int p2 = idx % 192, k = idx / 192;
        float dy = sOm[p2*28 + 2*k];
        float dx = sOm[p2*28 + 2*k + 1];
        float mv = sOm[p2*28 + 18 + k];
        float mask = 1.0f / (1.0f + __expf(-mv));
        int ky = k / 3, kx = k % 3;
        float ys = (float)(h0 + (p2/96) - 1 + ky) + dy;
        float xs = (float)((p2%96) - 1 + kx) + dx;
        float4 cf; int2 bs;
        make_meta(ys, xs, mask, cf, bs);
        int gi = (b*9 + k)*HW + h0*Wdim + p2;
        __half2 h01 = __floats2half2_rn(cf.x, cf.y);
        __half2 h23 = __floats2half2_rn(cf.z, cf.w);
        uint2 u;
        u.x = *(uint32_t*)&h01;
        u.y = *(uint32_t*)&h23;
        g_cfh[gi] = u;
        g_bs[gi]  = bs;
    }
}

// ---------------------------------------------------------------------------
// Kernel C: fused fp16 bilinear sample + mma.sync m16n8k16 GEMM. 2 blocks/SM.
// (reverted to the proven launch bounds; round-15's 3 blocks/SM spilled)
// ---------------------------------------------------------------------------
#define C_SS0    0
#define C_SS1    18432
#define C_SB0    36864
#define C_SB1    45056
#define C_SMEM_BYTES 53248

__global__ __launch_bounds__(256, 2)
void dc_main(const float* __restrict__ bias, float* __restrict__ out)
{
    extern __shared__ char smc[];
    unsigned smem_base = (unsigned)__cvta_generic_to_shared(smc);

    int tid = threadIdx.x;
    int wid = tid >> 5, lane = tid & 31;
    int g = lane >> 2, t = lane & 3;
    int b      = blockIdx.x / 72;
    int pxBase = (blockIdx.x % 72) * 128;
    const __half* xh = g_xt + (size_t)b * HW * 64;
    int warpPx0 = wid * 16;
    int mq = wid & 3, oh = wid >> 2;
    int px0m = mq * 32;

    int gsel = lane >> 4;
    int gcol = (lane >> 3) & 1;
    int goct = lane & 7;

    int rowl = (lane & 7) + (((lane >> 3) & 1) << 3);
    unsigned aOff0 = (unsigned)((px0m + rowl) * 144 + ((lane >> 4) << 4));
    unsigned aOff1 = aOff0 + 16u*144u;

    float4 acc[8];
    #pragma unroll
    for (int a = 0; a < 8; a++) acc[a] = make_float4(0.f,0.f,0.f,0.f);

    const uint4* Bg = g_wtmh;

    auto gather_pair = [&](const int2* bsp, const uint2* cfp, int p0, unsigned dstOff) {
        int myPx = p0 + gsel;
        int2  bs = __ldg(&bsp[myPx]);
        uint2 cf = __ldg(&cfp[myPx]);
        const __half* r0 = xh + bs.x + gcol*64 + goct*8;
        const __half* r1 = xh + bs.y + gcol*64 + goct*8;
        uint4 qA = *(const uint4*)r0;
        uint4 qB = *(const uint4*)r1;
        __half2 cfx = *(__half2*)&cf.x;
        __half2 cfy = *(__half2*)&cf.y;
        __half2 cA = __half2half2(gcol ? __high2half(cfx) : __low2half(cfx));
        __half2 cB = __half2half2(gcol ? __high2half(cfy) : __low2half(cfy));
        __half2 v0 = __hfma2(*(__half2*)&qB.x, cB, __hmul2(*(__half2*)&qA.x, cA));
        __half2 v1 = __hfma2(*(__half2*)&qB.y, cB, __hmul2(*(__half2*)&qA.y, cA));
        __half2 v2 = __hfma2(*(__half2*)&qB.z, cB, __hmul2(*(__half2*)&qA.z, cA));
        __half2 v3 = __hfma2(*(__half2*)&qB.w, cB, __hmul2(*(__half2*)&qA.w, cA));
        uint32_t u0 = __shfl_xor_sync(0xffffffffu, *(uint32_t*)&v0, 8);
        uint32_t u1 = __shfl_xor_sync(0xffffffffu, *(uint32_t*)&v1, 8);
        uint32_t u2 = __shfl_xor_sync(0xffffffffu, *(uint32_t*)&v2, 8);
        uint32_t u3 = __shfl_xor_sync(0xffffffffu, *(uint32_t*)&v3, 8);
        __half2 w0 = __hadd2(v0, *(__half2*)&u0);
        __half2 w1 = __hadd2(v1, *(__half2*)&u1);
        __half2 w2 = __hadd2(v2, *(__half2*)&u2);
        __half2 w3 = __hadd2(v3, *(__half2*)&u3);
        if ((lane & 8) == 0) {
            unsigned addr = smem_base + dstOff + (unsigned)(myPx*144 + goct*16);
            asm volatile("st.shared.v4.b32 [%0], {%1, %2, %3, %4};"
                :: "r"(addr), "r"(*(uint32_t*)&w0), "r"(*(uint32_t*)&w1),
                   "r"(*(uint32_t*)&w2), "r"(*(uint32_t*)&w3));
        }
    };

    for (int i = tid; i < 512; i += 256)
        cp_async16(smem_base + C_SB0 + (unsigned)i*16u, Bg + i);
    cp_commit();
    {
        const int2*  bsp = g_bs  + (size_t)(b*9 + 0)*HW + pxBase;
        const uint2* cfp = g_cfh + (size_t)(b*9 + 0)*HW + pxBase;
        #pragma unroll
        for (int pq = 0; pq < 8; pq++)
            gather_pair(bsp, cfp, warpPx0 + pq*2, C_SS0);
    }
    cp_wait0();
    __syncthreads();

    for (int k = 0; k < 9; k++) {
        int cur = k & 1, nxt = cur ^ 1;
        if (k < 8) {
            unsigned dstB = smem_base + (nxt ? C_SB1 : C_SB0);
            const uint4* srcB = Bg + (size_t)(k+1)*512;
            for (int i = tid; i < 512; i += 256)
                cp_async16(dstB + (unsigned)i*16u, srcB + i);
            cp_commit();
        }
        unsigned ssAddr = smem_base + (cur ? C_SS1 : C_SS0);
        const uint4* sB4 = (const uint4*)(smc + (cur ? C_SB1 : C_SB0));
        unsigned gdst = (unsigned)(nxt ? C_SS1 : C_SS0);
        int kn = (k+1 < 9) ? k+1 : 0;
        const int2*  bsp = g_bs  + (size_t)(b*9 + kn)*HW + pxBase;
        const uint2* cfp = g_cfh + (size_t)(b*9 + kn)*HW + pxBase;

        #pragma unroll
        for (int ch = 0; ch < 4; ch++) {
            if (k < 8) {
                gather_pair(bsp, cfp, warpPx0 + ch*4,     gdst);
                gather_pair(bsp, cfp, warpPx0 + ch*4 + 2, gdst);
            }
            {
                uint32_t a00, a01, a02, a03, a10, a11, a12, a13;
                ldmA(a00, a01, a02, a03, ssAddr + aOff0 + (unsigned)ch*32u);
                ldmA(a10, a11, a12, a13, ssAddr + aOff1 + (unsigned)ch*32u);
                uint4 bq0 = sB4[(ch*4 + 2*oh    )*32 + lane];
                uint4 bq1 = sB4[(ch*4 + 2*oh + 1)*32 + lane];
                mma_f16(acc[0], a00,a01,a02,a03, bq0.x, bq0.y);
                mma_f16(acc[1], a00,a01,a02,a03, bq0.z, bq0.w);
                mma_f16(acc[2], a00,a01,a02,a03, bq1.x, bq1.y);
                mma_f16(acc[3], a00,a01,a02,a03, bq1.z, bq1.w);
                mma_f16(acc[4], a10,a11,a12,a13, bq0.x, bq0.y);
                mma_f16(acc[5], a10,a11,a12,a13, bq0.z, bq0.w);
                mma_f16(acc[6], a10,a11,a12,a13, bq1.x, bq1.y);
                mma_f16(acc[7], a10,a11,a12,a13, bq1.z, bq1.w);
            }
        }
        cp_wait0();
        __syncthreads();
    }

    float* sOut = (float*)smc;
    #pragma unroll
    for (int mt = 0; mt < 2; mt++)
        #pragma unroll
        for (int nt = 0; nt < 4; nt++) {
            float4 dv = acc[mt*4 + nt];
            int o = oh*32 + nt*8 + 2*t;
            int pA = px0m + mt*16 + g, pB = pA + 8;
            sOut[o*132 + pA]     = dv.x;
            sOut[(o+1)*132 + pA] = dv.y;
            sOut[o*132 + pB]     = dv.z;
            sOut[(o+1)*132 + pB] = dv.w;
        }
    __syncthreads();
    float* ob = out + (size_t)b * COUT * HW + pxBase;
    for (int i = tid; i < 64*128; i += 256) {
        int o = i >> 7, p = i & 127;
        ob[(size_t)o*HW + p] = sOut[o*132 + p] + __ldg(&bias[o]);
    }
}

// ---------------------------------------------------------------------------
extern "C" void kernel_launch(void* const* d_in, const int* in_sizes, int n_in,
                              void* d_out, int out_size)
{
    const float* x      = (const float*)d_in[0];
    const float* w_off  = (const float*)d_in[1];
    const float* b_off  = (const float*)d_in[2];
    const float* weight = (const float*)d_in[3];
    const float* bias   = (const float*)d_in[4];
    float* out = (float*)d_out;

    static bool attr_done = false;
    if (!attr_done) {
        cudaFuncSetAttribute(dc_offsets, cudaFuncAttributeMaxDynamicSharedMemorySize,
                             B_SMEM_BYTES);
        cudaFuncSetAttribute(dc_main, cudaFuncAttributeMaxDynamicSharedMemorySize,
                             C_SMEM_BYTES);
        attr_done = true;
    }

    dc_prep    <<<1152 + 18, 256>>>(x, weight, w_off);
    dc_offsets <<<Bdim * (Hdim/2), 384, B_SMEM_BYTES>>>(b_off);
    dc_main    <<<Bdim * 72, 256, C_SMEM_BYTES>>>(bias, out);
}